// round 14
// baseline (speedup 1.0000x reference)
#include <cuda_runtime.h>
#include <cuda_bf16.h>
#include <cuda_fp16.h>
#include <cstdint>
#include <math.h>

// Problem constants
#define B_    2048
#define HW    256
#define SE_   8
#define CE_   16
#define ESZ_  512
#define NZ_   512

// Linear job layout: 592 full jobs (2 exact waves on 296 workers) + 192 quarter jobs.
#define NJOBS 784
#define LO_SCALE 2048.0f
#define LO_INV   (1.0f / 2048.0f)

// ---------------- scratch (static device globals; no allocation) ----------------
__device__ float g_table[14 * 8];
__device__ float g_se[(size_t)B_ * CE_ * HW];
__device__ float g_de[(size_t)B_ * CE_ * HW];
__device__ __nv_bfloat16 g_ahi[2 * (size_t)B_ * 8192];   // tw0 region holds fp16 bits
__device__ __nv_bfloat16 g_alo[2 * (size_t)B_ * 8192];   // tw0 region holds fp16(2048*lo)
__device__ __nv_bfloat16 g_whi[2 * (size_t)ESZ_ * 8192]; // tw0 region holds fp16 bits
__device__ __nv_bfloat16 g_wlo[2 * (size_t)ESZ_ * 8192]; // tw0 region unused
__device__ float g_partk[13 * (size_t)B_ * ESZ_];        // 13 K-chunk slots
__device__ __nv_bfloat16 g_eh[2 * (size_t)B_ * ESZ_];    // tw0 region holds fp16 bits
__device__ __nv_bfloat16 g_el[2 * (size_t)B_ * ESZ_];    // tw0 region holds fp16(2048*lo)
__device__ __nv_bfloat16 g_znh[NZ_ * ESZ_];
__device__ __nv_bfloat16 g_znl[NZ_ * ESZ_];
__device__ __half        g_znf[NZ_ * ESZ_];              // fp16 zn for final GEMM
__device__ float g_scores[(size_t)B_ * NZ_];
__device__ int   g_zind[B_];
__device__ float g_escale;
__device__ int   g_jobctr;

__device__ __forceinline__ uint32_t smem_u32(const void* p) {
    uint32_t a;
    asm("{ .reg .u64 t; cvta.to.shared.u64 t, %1; cvt.u32.u64 %0, t; }" : "=r"(a) : "l"(p));
    return a;
}

#define LDMATRIX_X4(r0, r1, r2, r3, addr) \
    asm volatile("ldmatrix.sync.aligned.m8n8.x4.shared.b16 {%0,%1,%2,%3}, [%4];" \
        : "=r"(r0), "=r"(r1), "=r"(r2), "=r"(r3) : "r"(addr))

#define MMA_BF16(d, a, b0, b1) \
    asm volatile("mma.sync.aligned.m16n8k16.row.col.f32.bf16.bf16.f32 " \
        "{%0,%1,%2,%3}, {%4,%5,%6,%7}, {%8,%9}, {%0,%1,%2,%3};" \
        : "+f"((d)[0]), "+f"((d)[1]), "+f"((d)[2]), "+f"((d)[3]) \
        : "r"((a)[0]), "r"((a)[1]), "r"((a)[2]), "r"((a)[3]), "r"(b0), "r"(b1))

#define MMA_F16(d, a, b0, b1) \
    asm volatile("mma.sync.aligned.m16n8k16.row.col.f32.f16.f16.f32 " \
        "{%0,%1,%2,%3}, {%4,%5,%6,%7}, {%8,%9}, {%0,%1,%2,%3};" \
        : "+f"((d)[0]), "+f"((d)[1]), "+f"((d)[2]), "+f"((d)[3]) \
        : "r"((a)[0]), "r"((a)[1]), "r"((a)[2]), "r"((a)[3]), "r"(b0), "r"(b1))

#define CP_ASYNC16(dst, src) \
    asm volatile("cp.async.cg.shared.global [%0], [%1], 16;" :: "r"(dst), "l"(src) : "memory")

__device__ __forceinline__ void split_bf16(float v, __nv_bfloat16& h, __nv_bfloat16& l) {
    h = __float2bfloat16(v);
    l = __float2bfloat16(v - __bfloat162float(h));
}

// ---------------- prep: normalize z rows (bf16 hi/lo + fp16), table, exp(scale), job ctr ----------------
__global__ void prep_kernel(const float* __restrict__ state_embed,
                            const float* __restrict__ zv,
                            const float* __restrict__ scale)
{
    int t = threadIdx.x;
    int blk = blockIdx.x;
    if (blk < NZ_) {
        __shared__ float red[128];
        const float* zr = zv + (size_t)blk * ESZ_;
        float v[4];
        float s = 0.f;
        #pragma unroll
        for (int i = 0; i < 4; i++) { v[i] = zr[t + i * 128]; s += v[i] * v[i]; }
        red[t] = s; __syncthreads();
        for (int off = 64; off > 0; off >>= 1) {
            if (t < off) red[t] += red[t + off];
            __syncthreads();
        }
        float inv = 1.0f / sqrtf(red[0]);
        #pragma unroll
        for (int i = 0; i < 4; i++) {
            float nv = v[i] * inv;
            __nv_bfloat16 h, l;
            split_bf16(nv, h, l);
            g_znh[(size_t)blk * ESZ_ + t + i * 128] = h;
            g_znl[(size_t)blk * ESZ_ + t + i * 128] = l;
            g_znf[(size_t)blk * ESZ_ + t + i * 128] = __float2half_rn(nv);
        }
    } else {
        if (t < 14) {
            float s = 0.f;
            #pragma unroll
            for (int j = 0; j < 8; j++) { float x = state_embed[t * 8 + j]; s += x * x; }
            float d = fmaxf(sqrtf(s), 1.0f);
            #pragma unroll
            for (int j = 0; j < 8; j++) g_table[t * 8 + j] = state_embed[t * 8 + j] / d;
        }
        if (t == 0) { g_escale = expf(scale[0]); g_jobctr = 0; }
    }
}

// ---------------- embed gather + 3x3 conv (8ch -> 16ch), fused for s and (s'-s) ----------------
__global__ __launch_bounds__(256) void embed_kernel(
    const int* __restrict__ s, const int* __restrict__ sp,
    const float* __restrict__ cw, const float* __restrict__ cb)
{
    __shared__ float tab[14 * 8];
    __shared__ float w[CE_ * SE_ * 9];
    __shared__ float bias[CE_];
    __shared__ float xs[SE_ * 324];
    __shared__ float xd[SE_ * 324];

    int tid = threadIdx.x;
    int b = blockIdx.x;

    if (tid < 112) tab[tid] = g_table[tid];
    for (int i = tid; i < CE_ * SE_ * 9; i += 256) w[i] = cw[i];
    if (tid < CE_) bias[tid] = cb[tid];
    for (int i = tid; i < SE_ * 324; i += 256) { xs[i] = 0.f; xd[i] = 0.f; }
    __syncthreads();

    int py0 = tid >> 4, px0 = tid & 15;
    int sv  = s[(size_t)b * HW + tid];
    int spv = sp[(size_t)b * HW + tid];
    #pragma unroll
    for (int ic = 0; ic < SE_; ic++) {
        float a = tab[sv * 8 + ic];
        float c = tab[spv * 8 + ic];
        int o = ic * 324 + (py0 + 1) * 18 + px0 + 1;
        xs[o] = a;
        xd[o] = c - a;
    }
    __syncthreads();

    int ocg = tid >> 6;
    int y   = (tid >> 2) & 15;
    int xg  = (tid & 3) * 4;

    float as[4][4] = {}, ad[4][4] = {};
    #pragma unroll
    for (int ic = 0; ic < SE_; ic++) {
        const float* ps = xs + ic * 324 + y * 18 + xg;
        const float* pd = xd + ic * 324 + y * 18 + xg;
        #pragma unroll
        for (int dy = 0; dy < 3; dy++)
        #pragma unroll
        for (int dx = 0; dx < 3; dx++) {
            int off = dy * 18 + dx;
            float s0 = ps[off], s1 = ps[off + 1], s2 = ps[off + 2], s3 = ps[off + 3];
            float d0 = pd[off], d1 = pd[off + 1], d2 = pd[off + 2], d3 = pd[off + 3];
            #pragma unroll
            for (int j = 0; j < 4; j++) {
                float wv = w[(ocg * 4 + j) * 72 + ic * 9 + dy * 3 + dx];
                as[j][0] += wv * s0; as[j][1] += wv * s1; as[j][2] += wv * s2; as[j][3] += wv * s3;
                ad[j][0] += wv * d0; ad[j][1] += wv * d1; ad[j][2] += wv * d2; ad[j][3] += wv * d3;
            }
        }
    }
    #pragma unroll
    for (int j = 0; j < 4; j++) {
        int oc = ocg * 4 + j;
        float bb = bias[oc];
        size_t o = ((size_t)b * CE_ + oc) * HW + y * 16 + xg;
        float4 v1 = make_float4(as[j][0] + bb, as[j][1] + bb, as[j][2] + bb, as[j][3] + bb);
        float4 v2 = make_float4(ad[j][0], ad[j][1], ad[j][2], ad[j][3]);
        *(float4*)(g_se + o) = v1;
        *(float4*)(g_de + o) = v2;
    }
}

// ---------------- fused tower: weights via __ldg (smem only for activations) ----------------
#define TOWER_SMEM_FLOATS (5184 * 2 + 48)
#define TOWER_SMEM_BYTES  (TOWER_SMEM_FLOATS * 4)

__global__ __launch_bounds__(256) void tower_kernel(
    const float* __restrict__ w1a, const float* __restrict__ b1a,
    const float* __restrict__ w2a, const float* __restrict__ b2a,
    const float* __restrict__ w1b, const float* __restrict__ b1b,
    const float* __restrict__ w2b, const float* __restrict__ b2b)
{
    extern __shared__ float sm[];
    float* pin = sm;
    float* mid = sm + 5184;
    float* bb1 = sm + 10368;
    float* bb2 = sm + 10384;

    int tid = threadIdx.x;
    int b   = blockIdx.x;
    int tw  = blockIdx.y;

    const float* in  = tw ? g_de : g_se;
    const float* w1g = tw ? w1b : w1a;
    const float* b1g = tw ? b1b : b1a;
    const float* w2g = tw ? w2b : w2a;
    const float* b2g = tw ? b2b : b2a;

    for (int i = tid; i < 10368; i += 256) sm[i] = 0.f;
    if (tid < 16) bb1[tid] = b1g[tid];
    if (tid < 32) bb2[tid] = b2g[tid];
    __syncthreads();

    int py0 = tid >> 4, px0 = tid & 15;
    #pragma unroll
    for (int c = 0; c < 16; c++)
        pin[c * 324 + (py0 + 1) * 18 + px0 + 1] = in[((size_t)b * 16 + c) * HW + tid];
    __syncthreads();

    int ocg = tid >> 6;
    int y   = (tid >> 2) & 15;
    int xg  = (tid & 3) * 4;

    {
        float acc[4][4] = {};
        #pragma unroll
        for (int ic = 0; ic < 16; ic++) {
            const float* pi = pin + ic * 324 + y * 18 + xg;
            #pragma unroll
            for (int dy = 0; dy < 3; dy++)
            #pragma unroll
            for (int dx = 0; dx < 3; dx++) {
                int off = dy * 18 + dx;
                float v0 = pi[off], v1 = pi[off + 1], v2 = pi[off + 2], v3 = pi[off + 3];
                #pragma unroll
                for (int j = 0; j < 4; j++) {
                    float wv = __ldg(&w1g[(ocg * 4 + j) * 144 + ic * 9 + dy * 3 + dx]);
                    acc[j][0] += wv * v0; acc[j][1] += wv * v1;
                    acc[j][2] += wv * v2; acc[j][3] += wv * v3;
                }
            }
        }
        #pragma unroll
        for (int j = 0; j < 4; j++) {
            int oc = ocg * 4 + j;
            float bbv = bb1[oc];
            float* mp = mid + oc * 324 + (y + 1) * 18 + xg + 1;
            mp[0] = fmaxf(acc[j][0] + bbv, 0.f);
            mp[1] = fmaxf(acc[j][1] + bbv, 0.f);
            mp[2] = fmaxf(acc[j][2] + bbv, 0.f);
            mp[3] = fmaxf(acc[j][3] + bbv, 0.f);
        }
    }
    __syncthreads();

    {
        float a2[8][4] = {};
        #pragma unroll 2
        for (int ic = 0; ic < 16; ic++) {
            const float* pi = mid + ic * 324 + y * 18 + xg;
            #pragma unroll
            for (int dy = 0; dy < 3; dy++)
            #pragma unroll
            for (int dx = 0; dx < 3; dx++) {
                int off = dy * 18 + dx;
                float v0 = pi[off], v1 = pi[off + 1], v2 = pi[off + 2], v3 = pi[off + 3];
                #pragma unroll
                for (int j = 0; j < 8; j++) {
                    float wv = __ldg(&w2g[(ocg * 8 + j) * 144 + ic * 9 + dy * 3 + dx]);
                    a2[j][0] += wv * v0; a2[j][1] += wv * v1;
                    a2[j][2] += wv * v2; a2[j][3] += wv * v3;
                }
            }
        }
        size_t base = (size_t)tw * B_ * 8192 + (size_t)b * 8192;
        #pragma unroll
        for (int j = 0; j < 8; j++) {
            int oc = ocg * 8 + j;
            float bbv = bb2[oc];
            float v[4];
            v[0] = fmaxf(a2[j][0] + bbv, 0.f);
            v[1] = fmaxf(a2[j][1] + bbv, 0.f);
            v[2] = fmaxf(a2[j][2] + bbv, 0.f);
            v[3] = fmaxf(a2[j][3] + bbv, 0.f);
            size_t o = base + oc * HW + y * 16 + xg;
            if (tw == 0) {
                __half h[4], l[4];
                #pragma unroll
                for (int q = 0; q < 4; q++) {
                    h[q] = __float2half_rn(v[q]);
                    l[q] = __float2half_rn((v[q] - __half2float(h[q])) * LO_SCALE);
                }
                *reinterpret_cast<__half2*>(g_ahi + o)     = __halves2half2(h[0], h[1]);
                *reinterpret_cast<__half2*>(g_ahi + o + 2) = __halves2half2(h[2], h[3]);
                *reinterpret_cast<__half2*>(g_alo + o)     = __halves2half2(l[0], l[1]);
                *reinterpret_cast<__half2*>(g_alo + o + 2) = __halves2half2(l[2], l[3]);
            } else {
                __nv_bfloat16 h[4], l[4];
                #pragma unroll
                for (int q = 0; q < 4; q++) split_bf16(v[q], h[q], l[q]);
                *(__nv_bfloat162*)(g_ahi + o)     = __nv_bfloat162(h[0], h[1]);
                *(__nv_bfloat162*)(g_ahi + o + 2) = __nv_bfloat162(h[2], h[3]);
                *(__nv_bfloat162*)(g_alo + o)     = __nv_bfloat162(l[0], l[1]);
                *(__nv_bfloat162*)(g_alo + o + 2) = __nv_bfloat162(l[2], l[3]);
            }
        }
    }
}

// ---------------- weight split: w1 -> fp16 hi only; w2 -> bf16 hi/lo ----------------
__global__ __launch_bounds__(256) void wconv_kernel(
    const float* __restrict__ w1, const float* __restrict__ w2)
{
    size_t i4 = (size_t)blockIdx.x * 256 + threadIdx.x;
    const size_t half4 = (size_t)ESZ_ * 8192 / 4;
    bool isw1 = i4 < half4;
    const float* src = isw1 ? w1 : w2;
    size_t loc4 = isw1 ? i4 : i4 - half4;
    float4 v = *(const float4*)(src + loc4 * 4);
    float vv[4] = { v.x, v.y, v.z, v.w };
    size_t o = i4 * 4;
    if (isw1) {
        __half h[4];
        #pragma unroll
        for (int q = 0; q < 4; q++) h[q] = __float2half_rn(vv[q]);
        *reinterpret_cast<__half2*>(g_whi + o)     = __halves2half2(h[0], h[1]);
        *reinterpret_cast<__half2*>(g_whi + o + 2) = __halves2half2(h[2], h[3]);
    } else {
        __nv_bfloat16 h[4], l[4];
        #pragma unroll
        for (int q = 0; q < 4; q++) split_bf16(vv[q], h[q], l[q]);
        *(__nv_bfloat162*)(g_whi + o)     = __nv_bfloat162(h[0], h[1]);
        *(__nv_bfloat162*)(g_whi + o + 2) = __nv_bfloat162(h[2], h[3]);
        *(__nv_bfloat162*)(g_wlo + o)     = __nv_bfloat162(l[0], l[1]);
        *(__nv_bfloat162*)(g_wlo + o + 2) = __nv_bfloat162(l[2], l[3]);
    }
}

// ---------------- persistent HMMA linear: atomic job queue, 592 full + 192 quarter jobs ----------------
#define APITCH 40

template<bool F16>
__device__ __forceinline__ void do_compute(
    uint32_t aB, uint32_t bB, const uint32_t* aOff, const uint32_t* bOff,
    float acc[4][4][4])
{
    #pragma unroll
    for (int kh = 0; kh < 2; kh++) {
        uint32_t aF[4][4], bF[2][4];
        #pragma unroll
        for (int mt = 0; mt < 4; mt++)
            LDMATRIX_X4(aF[mt][0], aF[mt][1], aF[mt][2], aF[mt][3],
                        aB + aOff[mt] + kh * 32);
        #pragma unroll
        for (int p = 0; p < 2; p++)
            LDMATRIX_X4(bF[p][0], bF[p][1], bF[p][2], bF[p][3],
                        bB + bOff[p] + kh * 32);
        #pragma unroll
        for (int mt = 0; mt < 4; mt++)
            #pragma unroll
            for (int nt = 0; nt < 4; nt++) {
                if (F16) MMA_F16(acc[mt][nt], aF[mt],
                                 bF[nt >> 1][(nt & 1) * 2], bF[nt >> 1][(nt & 1) * 2 + 1]);
                else     MMA_BF16(acc[mt][nt], aF[mt],
                                 bF[nt >> 1][(nt & 1) * 2], bF[nt >> 1][(nt & 1) * 2 + 1]);
            }
    }
}

__global__ __launch_bounds__(256, 2) void hmma_linear_persist()
{
    __shared__ __align__(16) __nv_bfloat16 smA[2][128 * APITCH];
    __shared__ __align__(16) __nv_bfloat16 smW[2][128 * APITCH];
    __shared__ int s_job;

    int tid = threadIdx.x;
    int wid = tid >> 5;
    int lid = tid & 31;

    bool isA = tid < 128;
    int lrow = tid & 127;
    uint32_t dstBase[2];
    dstBase[0] = smem_u32(isA ? &smA[0][0] : &smW[0][0]) + lrow * (APITCH * 2);
    dstBase[1] = smem_u32(isA ? &smA[1][0] : &smW[1][0]) + lrow * (APITCH * 2);

    int mw = wid & 1, nw = wid >> 1;
    uint32_t aOff[4], bOff[2];
    #pragma unroll
    for (int mt = 0; mt < 4; mt++) {
        int row = mw * 64 + mt * 16 + (lid & 15);
        int k   = (lid >> 4) * 8;
        aOff[mt] = (uint32_t)(row * APITCH + k) * 2;
    }
    #pragma unroll
    for (int p = 0; p < 2; p++) {
        int n = nw * 32 + p * 16 + ((lid >> 4) & 1) * 8 + (lid & 7);
        int k = ((lid >> 3) & 1) * 8;
        bOff[p] = (uint32_t)(n * APITCH + k) * 2;
    }
    uint32_t aBase[2] = { smem_u32(&smA[0][0]), smem_u32(&smA[1][0]) };
    uint32_t bBase[2] = { smem_u32(&smW[0][0]), smem_u32(&smW[1][0]) };

    for (;;) {
        if (tid == 0) s_job = atomicAdd(&g_jobctr, 1);
        __syncthreads();
        int j = s_job;
        if (j >= NJOBS) break;

        int tw, chunk, tile, slot, niter;
        size_t kbase;
        if (j < 256) {
            tw = 0; chunk = j >> 6; tile = j & 63; slot = chunk;
            kbase = (size_t)(chunk & 1) * 4096; niter = 128;
        } else if (j < 592) {
            int j2 = j - 256;
            tw = 1; chunk = j2 >> 6; tile = j2 & 63; slot = 4 + chunk;
            kbase = (size_t)(chunk & 1) * 4096; niter = 128;
        } else {
            int q = j - 592;
            tw = 1; chunk = 5; tile = 16 + (q >> 2);
            int quarter = q & 3;
            slot = 9 + quarter;
            kbase = 4096 + (size_t)quarter * 1024;
            niter = 32;
        }
        int ph = chunk >> 1;
        int bn = (tile & 3) * 128;
        int bm = (tile >> 2) * 128;

        const __nv_bfloat16* Abuf;
        const __nv_bfloat16* Bbuf;
        if (tw == 0) {
            Abuf = (ph == 1) ? g_alo : g_ahi;
            Bbuf = g_whi;
        } else {
            Abuf = ((ph == 1) ? g_alo : g_ahi) + (size_t)B_ * 8192;
            Bbuf = ((ph == 2) ? g_wlo : g_whi) + (size_t)ESZ_ * 8192;
        }
        const __nv_bfloat16* src0 = isA
            ? (Abuf + (size_t)(bm + lrow) * 8192 + kbase)
            : (Bbuf + (size_t)(bn + lrow) * 8192 + kbase);

        float acc[4][4][4] = {};

        {
            uint32_t d = dstBase[0];
            CP_ASYNC16(d,      src0);
            CP_ASYNC16(d + 16, src0 + 8);
            CP_ASYNC16(d + 32, src0 + 16);
            CP_ASYNC16(d + 48, src0 + 24);
            asm volatile("cp.async.commit_group;" ::: "memory");
        }
        for (int i = 0; i < niter; i++) {
            int buf = i & 1;
            if (i + 1 < niter) {
                const __nv_bfloat16* s = src0 + (size_t)(i + 1) * 32;
                uint32_t d = dstBase[buf ^ 1];
                CP_ASYNC16(d,      s);
                CP_ASYNC16(d + 16, s + 8);
                CP_ASYNC16(d + 32, s + 16);
                CP_ASYNC16(d + 48, s + 24);
                asm volatile("cp.async.commit_group;" ::: "memory");
                asm volatile("cp.async.wait_group 1;" ::: "memory");
            } else {
                asm volatile("cp.async.wait_group 0;" ::: "memory");
            }
            __syncthreads();
            if (tw == 0) do_compute<true >(aBase[buf], bBase[buf], aOff, bOff, acc);
            else         do_compute<false>(aBase[buf], bBase[buf], aOff, bOff, acc);
            __syncthreads();
        }

        float* part = g_partk + (size_t)slot * B_ * ESZ_;
        int g = lid >> 2, tg = lid & 3;
        #pragma unroll
        for (int mt = 0; mt < 4; mt++) {
            int row = bm + mw * 64 + mt * 16 + g;
            #pragma unroll
            for (int nt = 0; nt < 4; nt++) {
                int col = bn + nw * 32 + nt * 8 + tg * 2;
                *(float2*)(part + (size_t)row * ESZ_ + col) =
                    make_float2(acc[mt][nt][0], acc[mt][nt][1]);
                *(float2*)(part + (size_t)(row + 8) * ESZ_ + col) =
                    make_float2(acc[mt][nt][2], acc[mt][nt][3]);
            }
        }
        __syncthreads();
    }
}

// ---------------- K-chunk reduce + bias + L2 normalize; tw0 -> fp16 hi/lo, tw1 -> bf16 ----------------
__global__ __launch_bounds__(128) void reduce_norm_kernel(
    const float* __restrict__ b1, const float* __restrict__ b2)
{
    int row = blockIdx.x;
    int tw  = row >> 11;
    int r   = row & 2047;
    const float* bias = tw ? b2 : b1;
    int t = threadIdx.x;

    float v[4];
    {
        float4 bb = *(const float4*)(bias + t * 4);
        v[0] = bb.x; v[1] = bb.y; v[2] = bb.z; v[3] = bb.w;
    }
    size_t roff = (size_t)r * ESZ_ + t * 4;
    if (tw == 0) {
        float hi[4] = {0, 0, 0, 0}, lo[4] = {0, 0, 0, 0};
        #pragma unroll
        for (int c = 0; c < 2; c++) {
            float4 p = *(const float4*)(g_partk + (size_t)c * B_ * ESZ_ + roff);
            hi[0] += p.x; hi[1] += p.y; hi[2] += p.z; hi[3] += p.w;
        }
        #pragma unroll
        for (int c = 2; c < 4; c++) {
            float4 p = *(const float4*)(g_partk + (size_t)c * B_ * ESZ_ + roff);
            lo[0] += p.x; lo[1] += p.y; lo[2] += p.z; lo[3] += p.w;
        }
        #pragma unroll
        for (int q = 0; q < 4; q++) v[q] += hi[q] + lo[q] * LO_INV;
    } else {
        #pragma unroll
        for (int c = 4; c < 13; c++) {
            float4 p = *(const float4*)(g_partk + (size_t)c * B_ * ESZ_ + roff);
            v[0] += p.x; v[1] += p.y; v[2] += p.z; v[3] += p.w;
        }
    }

    __shared__ float red[128];
    red[t] = v[0] * v[0] + v[1] * v[1] + v[2] * v[2] + v[3] * v[3];
    __syncthreads();
    for (int off = 64; off > 0; off >>= 1) {
        if (t < off) red[t] += red[t + off];
        __syncthreads();
    }
    float inv = 1.0f / (sqrtf(red[0]) + 1e-4f);
    size_t o = (size_t)row * ESZ_ + t * 4;
    if (tw == 0) {
        __half h[4], l[4];
        #pragma unroll
        for (int q = 0; q < 4; q++) {
            float nv = v[q] * inv;
            h[q] = __float2half_rn(nv);
            l[q] = __float2half_rn((nv - __half2float(h[q])) * LO_SCALE);
        }
        *reinterpret_cast<__half2*>(g_eh + o)     = __halves2half2(h[0], h[1]);
        *reinterpret_cast<__half2*>(g_eh + o + 2) = __halves2half2(h[2], h[3]);
        *reinterpret_cast<__half2*>(g_el + o)     = __halves2half2(l[0], l[1]);
        *reinterpret_cast<__half2*>(g_el + o + 2) = __halves2half2(l[2], l[3]);
    } else {
        __nv_bfloat16 h[4], l[4];
        #pragma unroll
        for (int q = 0; q < 4; q++) split_bf16(v[q] * inv, h[q], l[q]);
        *(__nv_bfloat162*)(g_eh + o)     = __nv_bfloat162(h[0], h[1]);
        *(__nv_bfloat162*)(g_eh + o + 2) = __nv_bfloat162(h[2], h[3]);
        *(__nv_bfloat162*)(g_el + o)     = __nv_bfloat162(l[0], l[1]);
        *(__nv_bfloat162*)(g_el + o + 2) = __nv_bfloat162(l[2], l[3]);
    }
}

// ---------------- scores GEMM: bf16 3-term (unchanged numeric path) ----------------
#define OUT_NK 48

__global__ __launch_bounds__(256, 2) void hmma_scores_kernel(
    const __nv_bfloat16* __restrict__ Ah, const __nv_bfloat16* __restrict__ Al,
    const __nv_bfloat16* __restrict__ Bh, const __nv_bfloat16* __restrict__ Bl,
    float* __restrict__ C, int N)
{
    __shared__ __align__(16) __nv_bfloat16 smA[2][128 * APITCH];
    __shared__ __align__(16) __nv_bfloat16 smW[2][128 * APITCH];

    int tid = threadIdx.x;
    int wid = tid >> 5;
    int lid = tid & 31;
    int bn = blockIdx.x * 128;
    int bm = blockIdx.y * 128;

    bool isA = tid < 128;
    int lrow = tid & 127;
    int grow = isA ? (bm + lrow) : (bn + lrow);
    const __nv_bfloat16* srcHi = (isA ? Ah : Bh) + (size_t)grow * ESZ_;
    const __nv_bfloat16* srcLo = (isA ? Al : Bl) + (size_t)grow * ESZ_;
    uint32_t dstBase[2];
    dstBase[0] = smem_u32(isA ? &smA[0][0] : &smW[0][0]) + lrow * (APITCH * 2);
    dstBase[1] = smem_u32(isA ? &smA[1][0] : &smW[1][0]) + lrow * (APITCH * 2);

    auto load_tile = [&](int buf, int kt) {
        int ph = kt >> 4;
        int ko = (kt & 15) * 32;
        const __nv_bfloat16* src =
            (isA ? (ph == 1 ? srcLo : srcHi) : (ph == 2 ? srcLo : srcHi)) + ko;
        uint32_t d = dstBase[buf];
        CP_ASYNC16(d,      src);
        CP_ASYNC16(d + 16, src + 8);
        CP_ASYNC16(d + 32, src + 16);
        CP_ASYNC16(d + 48, src + 24);
        asm volatile("cp.async.commit_group;" ::: "memory");
    };

    int mw = wid & 1, nw = wid >> 1;
    uint32_t aOff[4], bOff[2];
    #pragma unroll
    for (int mt = 0; mt < 4; mt++) {
        int row = mw * 64 + mt * 16 + (lid & 15);
        int k   = (lid >> 4) * 8;
        aOff[mt] = (uint32_t)(row * APITCH + k) * 2;
    }
    #pragma unroll
    for (int p = 0; p < 2; p++) {
        int n = nw * 32 + p * 16 + ((lid >> 4) & 1) * 8 + (lid & 7);
        int k = ((lid >> 3) & 1) * 8;
        bOff[p] = (uint32_t)(n * APITCH + k) * 2;
    }
    uint32_t aBase[2] = { smem_u32(&smA[0][0]), smem_u32(&smA[1][0]) };
    uint32_t bBase[2] = { smem_u32(&smW[0][0]), smem_u32(&smW[1][0]) };

    float acc[4][4][4] = {};

    load_tile(0, 0);
    for (int kt = 0; kt < OUT_NK; kt++) {
        int buf = kt & 1;
        if (kt + 1 < OUT_NK) {
            load_tile(buf ^ 1, kt + 1);
            asm volatile("cp.async.wait_group 1;" ::: "memory");
        } else {
            asm volatile("cp.async.wait_group 0;" ::: "memory");
        }
        __syncthreads();
        do_compute<false>(aBase[buf], bBase[buf], aOff, bOff, acc);
        __syncthreads();
    }

    int g = lid >> 2, tg = lid & 3;
    #pragma unroll
    for (int mt = 0; mt < 4; mt++) {
        int row = bm + mw * 64 + mt * 16 + g;
        #pragma unroll
        for (int nt = 0; nt < 4; nt++) {
            int col = bn + nw * 32 + nt * 8 + tg * 2;
            *(float2*)(C + (size_t)row * N + col) =
                make_float2(acc[mt][nt][0], acc[mt][nt][1]);
            *(float2*)(C + (size_t)(row + 8) * N + col) =
                make_float2(acc[mt][nt][2], acc[mt][nt][3]);
        }
    }
}

// ---------------- final GEMM: fp16 2-term, gathered B rows, exp(scale) ----------------
#define OUTF_NK 32

__global__ __launch_bounds__(256, 2) void hmma_final_f16_kernel(
    const __half* __restrict__ Ah, const __half* __restrict__ Al,
    const __half* __restrict__ Bh, float* __restrict__ C, int N)
{
    __shared__ __align__(16) __nv_bfloat16 smA[2][128 * APITCH];
    __shared__ __align__(16) __nv_bfloat16 smW[2][128 * APITCH];

    int tid = threadIdx.x;
    int wid = tid >> 5;
    int lid = tid & 31;
    int bn = blockIdx.x * 128;
    int bm = blockIdx.y * 128;

    bool isA = tid < 128;
    int lrow = tid & 127;
    int grow = isA ? (bm + lrow) : g_zind[bn + lrow];
    const __half* srcHi = (isA ? Ah : Bh) + (size_t)grow * ESZ_;
    const __half* srcLo = (isA ? Al : Bh) + (size_t)grow * ESZ_;   // B has no lo; unused for B
    uint32_t dstBase[2];
    dstBase[0] = smem_u32(isA ? &smA[0][0] : &smW[0][0]) + lrow * (APITCH * 2);
    dstBase[1] = smem_u32(isA ? &smA[1][0] : &smW[1][0]) + lrow * (APITCH * 2);

    auto load_tile = [&](int buf, int kt) {
        int ph = kt >> 4;                 // 0: A-lo phase, 1: A-hi phase; B always hi
        int ko = (kt & 15) * 32;
        const __half* src = (isA ? (ph == 0 ? srcLo : srcHi) : srcHi) + ko;
        uint32_t d = dstBase[buf];
        CP_ASYNC16(d,      src);
        CP_ASYNC16(d + 16, src + 8);
        CP_ASYNC16(d + 32, src + 16);
        CP_ASYNC16(d + 48, src + 24);
        asm volatile("cp.async.commit_group;" ::: "memory");
    };

    int mw = wid & 1, nw = wid >> 1;
    uint32_t aOff[4], bOff[2];
    #pragma unroll
    for (int mt = 0; mt < 4; mt++) {
        int row = mw * 64 + mt * 16 + (lid & 15);
        int k   = (lid >> 4) * 8;
        aOff[mt] = (uint32_t)(row * APITCH + k) * 2;
    }
    #pragma unroll
    for (int p = 0; p < 2; p++) {
        int n = nw * 32 + p * 16 + ((lid >> 4) & 1) * 8 + (lid & 7);
        int k = ((lid >> 3) & 1) * 8;
        bOff[p] = (uint32_t)(n * APITCH + k) * 2;
    }
    uint32_t aBase[2] = { smem_u32(&smA[0][0]), smem_u32(&smA[1][0]) };
    uint32_t bBase[2] = { smem_u32(&smW[0][0]), smem_u32(&smW[1][0]) };

    float acc[4][4][4] = {};

    load_tile(0, 0);
    for (int kt = 0; kt < OUTF_NK; kt++) {
        int buf = kt & 1;
        if (kt + 1 < OUTF_NK) {
            load_tile(buf ^ 1, kt + 1);
            asm volatile("cp.async.wait_group 1;" ::: "memory");
        } else {
            asm volatile("cp.async.wait_group 0;" ::: "memory");
        }
        __syncthreads();
        do_compute<true>(aBase[buf], bBase[buf], aOff, bOff, acc);
        if (kt == 15) {
            // end of lo phase: rescale accumulated lo·hi by 1/2048
            #pragma unroll
            for (int mt = 0; mt < 4; mt++)
                #pragma unroll
                for (int nt = 0; nt < 4; nt++)
                    #pragma unroll
                    for (int q = 0; q < 4; q++)
                        acc[mt][nt][q] *= LO_INV;
        }
        __syncthreads();
    }

    float alpha = g_escale;
    int g = lid >> 2, tg = lid & 3;
    #pragma unroll
    for (int mt = 0; mt < 4; mt++) {
        int row = bm + mw * 64 + mt * 16 + g;
        #pragma unroll
        for (int nt = 0; nt < 4; nt++) {
            int col = bn + nw * 32 + nt * 8 + tg * 2;
            *(float2*)(C + (size_t)row * N + col) =
                make_float2(acc[mt][nt][0] * alpha, acc[mt][nt][1] * alpha);
            *(float2*)(C + (size_t)(row + 8) * N + col) =
                make_float2(acc[mt][nt][2] * alpha, acc[mt][nt][3] * alpha);
        }
    }
}

// ---------------- argmax over scores rows (first-max tie-break) ----------------
__global__ void argmax_kernel()
{
    int r = blockIdx.x, t = threadIdx.x;
    const float* sr = g_scores + (size_t)r * NZ_;
    __shared__ float sv[256];
    __shared__ int   si[256];
    float v0 = sr[t], v1 = sr[t + 256];
    float bv = v0; int bi = t;
    if (v1 > bv) { bv = v1; bi = t + 256; }
    sv[t] = bv; si[t] = bi; __syncthreads();
    for (int off = 128; off > 0; off >>= 1) {
        if (t < off) {
            float ov = sv[t + off]; int oi = si[t + off];
            if (ov > sv[t] || (ov == sv[t] && oi < si[t])) { sv[t] = ov; si[t] = oi; }
        }
        __syncthreads();
    }
    if (t == 0) g_zind[r] = si[0];
}

// ---------------- launch ----------------
extern "C" void kernel_launch(void* const* d_in, const int* in_sizes, int n_in,
                              void* d_out, int out_size)
{
    (void)in_sizes; (void)n_in; (void)out_size;
    const int*   s       = (const int*)d_in[0];
    const int*   sp      = (const int*)d_in[1];
    const float* state_e = (const float*)d_in[2];
    const float* cew     = (const float*)d_in[3];
    const float* ceb     = (const float*)d_in[4];
    const float* p1c1w   = (const float*)d_in[5];
    const float* p1c1b   = (const float*)d_in[6];
    const float* p1c2w   = (const float*)d_in[7];
    const float* p1c2b   = (const float*)d_in[8];
    const float* p1lw    = (const float*)d_in[9];
    const float* p1lb    = (const float*)d_in[10];
    const float* p2c1w   = (const float*)d_in[11];
    const float* p2c1b   = (const float*)d_in[12];
    const float* p2c2w   = (const float*)d_in[13];
    const float* p2c2b   = (const float*)d_in[14];
    const float* p2lw    = (const float*)d_in[15];
    const float* p2lb    = (const float*)d_in[16];
    const float* zv      = (const float*)d_in[17];
    const float* scale   = (const float*)d_in[18];

    void *peh, *pel, *pzh, *pzl, *pzf, *ps, *pp;
    cudaGetSymbolAddress(&peh, g_eh);
    cudaGetSymbolAddress(&pel, g_el);
    cudaGetSymbolAddress(&pzh, g_znh);
    cudaGetSymbolAddress(&pzl, g_znl);
    cudaGetSymbolAddress(&pzf, g_znf);
    cudaGetSymbolAddress(&ps, g_scores);
    cudaGetSymbolAddress(&pp, g_partk);
    __nv_bfloat16* eh  = (__nv_bfloat16*)peh;
    __nv_bfloat16* el  = (__nv_bfloat16*)pel;
    __nv_bfloat16* znh = (__nv_bfloat16*)pzh;
    __nv_bfloat16* znl = (__nv_bfloat16*)pzl;
    __half*        znf = (__half*)pzf;
    float* scores = (float*)ps;
    float* partk  = (float*)pp;

    cudaFuncSetAttribute(tower_kernel,
                         cudaFuncAttributeMaxDynamicSharedMemorySize, TOWER_SMEM_BYTES);

    prep_kernel<<<513, 128>>>(state_e, zv, scale);
    embed_kernel<<<B_, 256>>>(s, sp, cew, ceb);
    wconv_kernel<<<(2 * ESZ_ * 8192 / 4) / 256, 256>>>(p1lw, p2lw);
    tower_kernel<<<dim3(B_, 2), 256, TOWER_SMEM_BYTES>>>(
        p1c1w, p1c1b, p1c2w, p1c2b, p2c1w, p2c1b, p2c2w, p2c2b);

    // zero extra tail slots 10..12 (regions not covered by quarter jobs must read 0)
    cudaMemsetAsync(partk + (size_t)10 * B_ * ESZ_, 0,
                    (size_t)3 * B_ * ESZ_ * sizeof(float));

    // persistent job-queue linear: 592 full jobs (2 exact waves) + 192 quarter tail jobs
    hmma_linear_persist<<<296, 256>>>();

    // K-chunk reduce + bias + normalize -> fp16 (tw0) / bf16 (tw1) hi/lo embeds
    reduce_norm_kernel<<<2 * B_, 128>>>(p1lb, p2lb);

    // scores = embed2 . zn^T (bf16 3-term, numeric path unchanged)
    hmma_scores_kernel<<<dim3(4, 16), 256>>>(
        eh + (size_t)B_ * ESZ_, el + (size_t)B_ * ESZ_, znh, znl, scores, NZ_);

    argmax_kernel<<<B_, 256>>>();

    // out = exp(scale) * embed1 . zn[z_inds]^T (fp16 2-term, gathered B rows)
    hmma_final_f16_kernel<<<dim3(16, 16), 256>>>(
        (const __half*)eh, (const __half*)el, znf, (float*)d_out, B_);
}

// round 16
// speedup vs baseline: 1.0505x; 1.0505x over previous
#include <cuda_runtime.h>
#include <cuda_bf16.h>
#include <cuda_fp16.h>
#include <cstdint>
#include <math.h>

// Problem constants
#define B_    2048
#define HW    256
#define SE_   8
#define CE_   16
#define ESZ_  512
#define NZ_   512

// Linear job layout: 592 full jobs (2 exact waves on 296 workers) + 192 quarter jobs.
#define NJOBS 784
#define LO_SCALE 2048.0f
#define LO_INV   (1.0f / 2048.0f)

// ---------------- scratch (static device globals; no allocation) ----------------
__device__ float g_table[14 * 8];
__device__ float g_se[(size_t)B_ * CE_ * HW];
__device__ float g_de[(size_t)B_ * CE_ * HW];
__device__ __nv_bfloat16 g_ahi[2 * (size_t)B_ * 8192];   // tw0 region holds fp16 bits
__device__ __nv_bfloat16 g_alo[2 * (size_t)B_ * 8192];   // tw0 region holds fp16(2048*lo)
__device__ __nv_bfloat16 g_whi[2 * (size_t)ESZ_ * 8192]; // tw0 region holds fp16 bits
__device__ __nv_bfloat16 g_wlo[2 * (size_t)ESZ_ * 8192]; // tw0 region unused
__device__ float g_partk[13 * (size_t)B_ * ESZ_];        // 13 K-chunk slots
__device__ __nv_bfloat16 g_eh[2 * (size_t)B_ * ESZ_];    // tw0 region holds fp16 bits
__device__ __nv_bfloat16 g_el[2 * (size_t)B_ * ESZ_];    // tw0 region holds fp16(2048*lo)
__device__ __nv_bfloat16 g_znh[NZ_ * ESZ_];
__device__ __nv_bfloat16 g_znl[NZ_ * ESZ_];
__device__ __half        g_znf[NZ_ * ESZ_];              // fp16 zn for final GEMM
__device__ float g_scores[(size_t)B_ * NZ_];
__device__ int   g_zind[B_];
__device__ float g_escale;
__device__ int   g_jobctr;

__device__ __forceinline__ uint32_t smem_u32(const void* p) {
    uint32_t a;
    asm("{ .reg .u64 t; cvta.to.shared.u64 t, %1; cvt.u32.u64 %0, t; }" : "=r"(a) : "l"(p));
    return a;
}

#define LDMATRIX_X4(r0, r1, r2, r3, addr) \
    asm volatile("ldmatrix.sync.aligned.m8n8.x4.shared.b16 {%0,%1,%2,%3}, [%4];" \
        : "=r"(r0), "=r"(r1), "=r"(r2), "=r"(r3) : "r"(addr))

#define MMA_BF16(d, a, b0, b1) \
    asm volatile("mma.sync.aligned.m16n8k16.row.col.f32.bf16.bf16.f32 " \
        "{%0,%1,%2,%3}, {%4,%5,%6,%7}, {%8,%9}, {%0,%1,%2,%3};" \
        : "+f"((d)[0]), "+f"((d)[1]), "+f"((d)[2]), "+f"((d)[3]) \
        : "r"((a)[0]), "r"((a)[1]), "r"((a)[2]), "r"((a)[3]), "r"(b0), "r"(b1))

#define MMA_F16(d, a, b0, b1) \
    asm volatile("mma.sync.aligned.m16n8k16.row.col.f32.f16.f16.f32 " \
        "{%0,%1,%2,%3}, {%4,%5,%6,%7}, {%8,%9}, {%0,%1,%2,%3};" \
        : "+f"((d)[0]), "+f"((d)[1]), "+f"((d)[2]), "+f"((d)[3]) \
        : "r"((a)[0]), "r"((a)[1]), "r"((a)[2]), "r"((a)[3]), "r"(b0), "r"(b1))

#define CP_ASYNC16(dst, src) \
    asm volatile("cp.async.cg.shared.global [%0], [%1], 16;" :: "r"(dst), "l"(src) : "memory")

__device__ __forceinline__ void split_bf16(float v, __nv_bfloat16& h, __nv_bfloat16& l) {
    h = __float2bfloat16(v);
    l = __float2bfloat16(v - __bfloat162float(h));
}

// ---------------- prep: normalize z rows (bf16 hi/lo + fp16), table, exp(scale), job ctr ----------------
__global__ void prep_kernel(const float* __restrict__ state_embed,
                            const float* __restrict__ zv,
                            const float* __restrict__ scale)
{
    int t = threadIdx.x;
    int blk = blockIdx.x;
    if (blk < NZ_) {
        __shared__ float red[128];
        const float* zr = zv + (size_t)blk * ESZ_;
        float v[4];
        float s = 0.f;
        #pragma unroll
        for (int i = 0; i < 4; i++) { v[i] = zr[t + i * 128]; s += v[i] * v[i]; }
        red[t] = s; __syncthreads();
        for (int off = 64; off > 0; off >>= 1) {
            if (t < off) red[t] += red[t + off];
            __syncthreads();
        }
        float inv = 1.0f / sqrtf(red[0]);
        #pragma unroll
        for (int i = 0; i < 4; i++) {
            float nv = v[i] * inv;
            __nv_bfloat16 h, l;
            split_bf16(nv, h, l);
            g_znh[(size_t)blk * ESZ_ + t + i * 128] = h;
            g_znl[(size_t)blk * ESZ_ + t + i * 128] = l;
            g_znf[(size_t)blk * ESZ_ + t + i * 128] = __float2half_rn(nv);
        }
    } else {
        if (t < 14) {
            float s = 0.f;
            #pragma unroll
            for (int j = 0; j < 8; j++) { float x = state_embed[t * 8 + j]; s += x * x; }
            float d = fmaxf(sqrtf(s), 1.0f);
            #pragma unroll
            for (int j = 0; j < 8; j++) g_table[t * 8 + j] = state_embed[t * 8 + j] / d;
        }
        if (t == 0) { g_escale = expf(scale[0]); g_jobctr = 0; }
    }
}

// ---------------- embed gather + 3x3 conv (8ch -> 16ch), fused for s and (s'-s) ----------------
__global__ __launch_bounds__(256) void embed_kernel(
    const int* __restrict__ s, const int* __restrict__ sp,
    const float* __restrict__ cw, const float* __restrict__ cb)
{
    __shared__ float tab[14 * 8];
    __shared__ float w[CE_ * SE_ * 9];
    __shared__ float bias[CE_];
    __shared__ float xs[SE_ * 324];
    __shared__ float xd[SE_ * 324];

    int tid = threadIdx.x;
    int b = blockIdx.x;

    if (tid < 112) tab[tid] = g_table[tid];
    for (int i = tid; i < CE_ * SE_ * 9; i += 256) w[i] = cw[i];
    if (tid < CE_) bias[tid] = cb[tid];
    for (int i = tid; i < SE_ * 324; i += 256) { xs[i] = 0.f; xd[i] = 0.f; }
    __syncthreads();

    int py0 = tid >> 4, px0 = tid & 15;
    int sv  = s[(size_t)b * HW + tid];
    int spv = sp[(size_t)b * HW + tid];
    #pragma unroll
    for (int ic = 0; ic < SE_; ic++) {
        float a = tab[sv * 8 + ic];
        float c = tab[spv * 8 + ic];
        int o = ic * 324 + (py0 + 1) * 18 + px0 + 1;
        xs[o] = a;
        xd[o] = c - a;
    }
    __syncthreads();

    int ocg = tid >> 6;
    int y   = (tid >> 2) & 15;
    int xg  = (tid & 3) * 4;

    float as[4][4] = {}, ad[4][4] = {};
    #pragma unroll
    for (int ic = 0; ic < SE_; ic++) {
        const float* ps = xs + ic * 324 + y * 18 + xg;
        const float* pd = xd + ic * 324 + y * 18 + xg;
        #pragma unroll
        for (int dy = 0; dy < 3; dy++)
        #pragma unroll
        for (int dx = 0; dx < 3; dx++) {
            int off = dy * 18 + dx;
            float s0 = ps[off], s1 = ps[off + 1], s2 = ps[off + 2], s3 = ps[off + 3];
            float d0 = pd[off], d1 = pd[off + 1], d2 = pd[off + 2], d3 = pd[off + 3];
            #pragma unroll
            for (int j = 0; j < 4; j++) {
                float wv = w[(ocg * 4 + j) * 72 + ic * 9 + dy * 3 + dx];
                as[j][0] += wv * s0; as[j][1] += wv * s1; as[j][2] += wv * s2; as[j][3] += wv * s3;
                ad[j][0] += wv * d0; ad[j][1] += wv * d1; ad[j][2] += wv * d2; ad[j][3] += wv * d3;
            }
        }
    }
    #pragma unroll
    for (int j = 0; j < 4; j++) {
        int oc = ocg * 4 + j;
        float bb = bias[oc];
        size_t o = ((size_t)b * CE_ + oc) * HW + y * 16 + xg;
        float4 v1 = make_float4(as[j][0] + bb, as[j][1] + bb, as[j][2] + bb, as[j][3] + bb);
        float4 v2 = make_float4(ad[j][0], ad[j][1], ad[j][2], ad[j][3]);
        *(float4*)(g_se + o) = v1;
        *(float4*)(g_de + o) = v2;
    }
}

// ---------------- fused tower (R13 smem-weights version): conv1+relu, conv2+relu ----------------
#define TOWER_SMEM_FLOATS (5184 * 2 + 2304 + 4608 + 16 + 32)
#define TOWER_SMEM_BYTES  (TOWER_SMEM_FLOATS * 4)

__global__ __launch_bounds__(256) void tower_kernel(
    const float* __restrict__ w1a, const float* __restrict__ b1a,
    const float* __restrict__ w2a, const float* __restrict__ b2a,
    const float* __restrict__ w1b, const float* __restrict__ b1b,
    const float* __restrict__ w2b, const float* __restrict__ b2b)
{
    extern __shared__ float sm[];
    float* pin = sm;
    float* mid = sm + 5184;
    float* w1  = sm + 10368;
    float* w2  = sm + 12672;
    float* bb1 = sm + 17280;
    float* bb2 = sm + 17296;

    int tid = threadIdx.x;
    int b   = blockIdx.x;
    int tw  = blockIdx.y;

    const float* in  = tw ? g_de : g_se;
    const float* w1g = tw ? w1b : w1a;
    const float* b1g = tw ? b1b : b1a;
    const float* w2g = tw ? w2b : w2a;
    const float* b2g = tw ? b2b : b2a;

    for (int i = tid; i < 10368; i += 256) sm[i] = 0.f;
    for (int i = tid; i < 2304; i += 256) w1[i] = w1g[i];
    for (int i = tid; i < 4608; i += 256) w2[i] = w2g[i];
    if (tid < 16) bb1[tid] = b1g[tid];
    if (tid < 32) bb2[tid] = b2g[tid];
    __syncthreads();

    int py0 = tid >> 4, px0 = tid & 15;
    #pragma unroll
    for (int c = 0; c < 16; c++)
        pin[c * 324 + (py0 + 1) * 18 + px0 + 1] = in[((size_t)b * 16 + c) * HW + tid];
    __syncthreads();

    int ocg = tid >> 6;
    int y   = (tid >> 2) & 15;
    int xg  = (tid & 3) * 4;

    {
        float acc[4][4] = {};
        #pragma unroll
        for (int ic = 0; ic < 16; ic++) {
            const float* pi = pin + ic * 324 + y * 18 + xg;
            #pragma unroll
            for (int dy = 0; dy < 3; dy++)
            #pragma unroll
            for (int dx = 0; dx < 3; dx++) {
                int off = dy * 18 + dx;
                float v0 = pi[off], v1 = pi[off + 1], v2 = pi[off + 2], v3 = pi[off + 3];
                #pragma unroll
                for (int j = 0; j < 4; j++) {
                    float wv = w1[(ocg * 4 + j) * 144 + ic * 9 + dy * 3 + dx];
                    acc[j][0] += wv * v0; acc[j][1] += wv * v1;
                    acc[j][2] += wv * v2; acc[j][3] += wv * v3;
                }
            }
        }
        #pragma unroll
        for (int j = 0; j < 4; j++) {
            int oc = ocg * 4 + j;
            float bbv = bb1[oc];
            float* mp = mid + oc * 324 + (y + 1) * 18 + xg + 1;
            mp[0] = fmaxf(acc[j][0] + bbv, 0.f);
            mp[1] = fmaxf(acc[j][1] + bbv, 0.f);
            mp[2] = fmaxf(acc[j][2] + bbv, 0.f);
            mp[3] = fmaxf(acc[j][3] + bbv, 0.f);
        }
    }
    __syncthreads();

    {
        float a2[8][4] = {};
        #pragma unroll 2
        for (int ic = 0; ic < 16; ic++) {
            const float* pi = mid + ic * 324 + y * 18 + xg;
            #pragma unroll
            for (int dy = 0; dy < 3; dy++)
            #pragma unroll
            for (int dx = 0; dx < 3; dx++) {
                int off = dy * 18 + dx;
                float v0 = pi[off], v1 = pi[off + 1], v2 = pi[off + 2], v3 = pi[off + 3];
                #pragma unroll
                for (int j = 0; j < 8; j++) {
                    float wv = w2[(ocg * 8 + j) * 144 + ic * 9 + dy * 3 + dx];
                    a2[j][0] += wv * v0; a2[j][1] += wv * v1;
                    a2[j][2] += wv * v2; a2[j][3] += wv * v3;
                }
            }
        }
        size_t base = (size_t)tw * B_ * 8192 + (size_t)b * 8192;
        #pragma unroll
        for (int j = 0; j < 8; j++) {
            int oc = ocg * 8 + j;
            float bbv = bb2[oc];
            float v[4];
            v[0] = fmaxf(a2[j][0] + bbv, 0.f);
            v[1] = fmaxf(a2[j][1] + bbv, 0.f);
            v[2] = fmaxf(a2[j][2] + bbv, 0.f);
            v[3] = fmaxf(a2[j][3] + bbv, 0.f);
            size_t o = base + oc * HW + y * 16 + xg;
            if (tw == 0) {
                __half h[4], l[4];
                #pragma unroll
                for (int q = 0; q < 4; q++) {
                    h[q] = __float2half_rn(v[q]);
                    l[q] = __float2half_rn((v[q] - __half2float(h[q])) * LO_SCALE);
                }
                *reinterpret_cast<__half2*>(g_ahi + o)     = __halves2half2(h[0], h[1]);
                *reinterpret_cast<__half2*>(g_ahi + o + 2) = __halves2half2(h[2], h[3]);
                *reinterpret_cast<__half2*>(g_alo + o)     = __halves2half2(l[0], l[1]);
                *reinterpret_cast<__half2*>(g_alo + o + 2) = __halves2half2(l[2], l[3]);
            } else {
                __nv_bfloat16 h[4], l[4];
                #pragma unroll
                for (int q = 0; q < 4; q++) split_bf16(v[q], h[q], l[q]);
                *(__nv_bfloat162*)(g_ahi + o)     = __nv_bfloat162(h[0], h[1]);
                *(__nv_bfloat162*)(g_ahi + o + 2) = __nv_bfloat162(h[2], h[3]);
                *(__nv_bfloat162*)(g_alo + o)     = __nv_bfloat162(l[0], l[1]);
                *(__nv_bfloat162*)(g_alo + o + 2) = __nv_bfloat162(l[2], l[3]);
            }
        }
    }
}

// ---------------- weight split: w1 -> fp16 hi only; w2 -> bf16 hi/lo ----------------
__global__ __launch_bounds__(256) void wconv_kernel(
    const float* __restrict__ w1, const float* __restrict__ w2)
{
    size_t i4 = (size_t)blockIdx.x * 256 + threadIdx.x;
    const size_t half4 = (size_t)ESZ_ * 8192 / 4;
    bool isw1 = i4 < half4;
    const float* src = isw1 ? w1 : w2;
    size_t loc4 = isw1 ? i4 : i4 - half4;
    float4 v = *(const float4*)(src + loc4 * 4);
    float vv[4] = { v.x, v.y, v.z, v.w };
    size_t o = i4 * 4;
    if (isw1) {
        __half h[4];
        #pragma unroll
        for (int q = 0; q < 4; q++) h[q] = __float2half_rn(vv[q]);
        *reinterpret_cast<__half2*>(g_whi + o)     = __halves2half2(h[0], h[1]);
        *reinterpret_cast<__half2*>(g_whi + o + 2) = __halves2half2(h[2], h[3]);
    } else {
        __nv_bfloat16 h[4], l[4];
        #pragma unroll
        for (int q = 0; q < 4; q++) split_bf16(vv[q], h[q], l[q]);
        *(__nv_bfloat162*)(g_whi + o)     = __nv_bfloat162(h[0], h[1]);
        *(__nv_bfloat162*)(g_whi + o + 2) = __nv_bfloat162(h[2], h[3]);
        *(__nv_bfloat162*)(g_wlo + o)     = __nv_bfloat162(l[0], l[1]);
        *(__nv_bfloat162*)(g_wlo + o + 2) = __nv_bfloat162(l[2], l[3]);
    }
}

// ---------------- persistent HMMA linear: atomic job queue, 592 full + 192 quarter jobs ----------------
#define APITCH 40

template<bool F16>
__device__ __forceinline__ void do_compute(
    uint32_t aB, uint32_t bB, const uint32_t* aOff, const uint32_t* bOff,
    float acc[4][4][4])
{
    #pragma unroll
    for (int kh = 0; kh < 2; kh++) {
        uint32_t aF[4][4], bF[2][4];
        #pragma unroll
        for (int mt = 0; mt < 4; mt++)
            LDMATRIX_X4(aF[mt][0], aF[mt][1], aF[mt][2], aF[mt][3],
                        aB + aOff[mt] + kh * 32);
        #pragma unroll
        for (int p = 0; p < 2; p++)
            LDMATRIX_X4(bF[p][0], bF[p][1], bF[p][2], bF[p][3],
                        bB + bOff[p] + kh * 32);
        #pragma unroll
        for (int mt = 0; mt < 4; mt++)
            #pragma unroll
            for (int nt = 0; nt < 4; nt++) {
                if (F16) MMA_F16(acc[mt][nt], aF[mt],
                                 bF[nt >> 1][(nt & 1) * 2], bF[nt >> 1][(nt & 1) * 2 + 1]);
                else     MMA_BF16(acc[mt][nt], aF[mt],
                                 bF[nt >> 1][(nt & 1) * 2], bF[nt >> 1][(nt & 1) * 2 + 1]);
            }
    }
}

__global__ __launch_bounds__(256, 2) void hmma_linear_persist()
{
    __shared__ __align__(16) __nv_bfloat16 smA[2][128 * APITCH];
    __shared__ __align__(16) __nv_bfloat16 smW[2][128 * APITCH];
    __shared__ int s_job;

    int tid = threadIdx.x;
    int wid = tid >> 5;
    int lid = tid & 31;

    bool isA = tid < 128;
    int lrow = tid & 127;
    uint32_t dstBase[2];
    dstBase[0] = smem_u32(isA ? &smA[0][0] : &smW[0][0]) + lrow * (APITCH * 2);
    dstBase[1] = smem_u32(isA ? &smA[1][0] : &smW[1][0]) + lrow * (APITCH * 2);

    int mw = wid & 1, nw = wid >> 1;
    uint32_t aOff[4], bOff[2];
    #pragma unroll
    for (int mt = 0; mt < 4; mt++) {
        int row = mw * 64 + mt * 16 + (lid & 15);
        int k   = (lid >> 4) * 8;
        aOff[mt] = (uint32_t)(row * APITCH + k) * 2;
    }
    #pragma unroll
    for (int p = 0; p < 2; p++) {
        int n = nw * 32 + p * 16 + ((lid >> 4) & 1) * 8 + (lid & 7);
        int k = ((lid >> 3) & 1) * 8;
        bOff[p] = (uint32_t)(n * APITCH + k) * 2;
    }
    uint32_t aBase[2] = { smem_u32(&smA[0][0]), smem_u32(&smA[1][0]) };
    uint32_t bBase[2] = { smem_u32(&smW[0][0]), smem_u32(&smW[1][0]) };

    for (;;) {
        if (tid == 0) s_job = atomicAdd(&g_jobctr, 1);
        __syncthreads();
        int j = s_job;
        if (j >= NJOBS) break;

        int tw, chunk, tile, slot, niter;
        size_t kbase;
        if (j < 256) {
            tw = 0; chunk = j >> 6; tile = j & 63; slot = chunk;
            kbase = (size_t)(chunk & 1) * 4096; niter = 128;
        } else if (j < 592) {
            int j2 = j - 256;
            tw = 1; chunk = j2 >> 6; tile = j2 & 63; slot = 4 + chunk;
            kbase = (size_t)(chunk & 1) * 4096; niter = 128;
        } else {
            int q = j - 592;
            tw = 1; chunk = 5; tile = 16 + (q >> 2);
            int quarter = q & 3;
            slot = 9 + quarter;
            kbase = 4096 + (size_t)quarter * 1024;
            niter = 32;
        }
        int ph = chunk >> 1;
        int bn = (tile & 3) * 128;
        int bm = (tile >> 2) * 128;

        const __nv_bfloat16* Abuf;
        const __nv_bfloat16* Bbuf;
        if (tw == 0) {
            Abuf = (ph == 1) ? g_alo : g_ahi;
            Bbuf = g_whi;
        } else {
            Abuf = ((ph == 1) ? g_alo : g_ahi) + (size_t)B_ * 8192;
            Bbuf = ((ph == 2) ? g_wlo : g_whi) + (size_t)ESZ_ * 8192;
        }
        const __nv_bfloat16* src0 = isA
            ? (Abuf + (size_t)(bm + lrow) * 8192 + kbase)
            : (Bbuf + (size_t)(bn + lrow) * 8192 + kbase);

        float acc[4][4][4] = {};

        {
            uint32_t d = dstBase[0];
            CP_ASYNC16(d,      src0);
            CP_ASYNC16(d + 16, src0 + 8);
            CP_ASYNC16(d + 32, src0 + 16);
            CP_ASYNC16(d + 48, src0 + 24);
            asm volatile("cp.async.commit_group;" ::: "memory");
        }
        for (int i = 0; i < niter; i++) {
            int buf = i & 1;
            if (i + 1 < niter) {
                const __nv_bfloat16* s = src0 + (size_t)(i + 1) * 32;
                uint32_t d = dstBase[buf ^ 1];
                CP_ASYNC16(d,      s);
                CP_ASYNC16(d + 16, s + 8);
                CP_ASYNC16(d + 32, s + 16);
                CP_ASYNC16(d + 48, s + 24);
                asm volatile("cp.async.commit_group;" ::: "memory");
                asm volatile("cp.async.wait_group 1;" ::: "memory");
            } else {
                asm volatile("cp.async.wait_group 0;" ::: "memory");
            }
            __syncthreads();
            if (tw == 0) do_compute<true >(aBase[buf], bBase[buf], aOff, bOff, acc);
            else         do_compute<false>(aBase[buf], bBase[buf], aOff, bOff, acc);
            __syncthreads();
        }

        float* part = g_partk + (size_t)slot * B_ * ESZ_;
        int g = lid >> 2, tg = lid & 3;
        #pragma unroll
        for (int mt = 0; mt < 4; mt++) {
            int row = bm + mw * 64 + mt * 16 + g;
            #pragma unroll
            for (int nt = 0; nt < 4; nt++) {
                int col = bn + nw * 32 + nt * 8 + tg * 2;
                *(float2*)(part + (size_t)row * ESZ_ + col) =
                    make_float2(acc[mt][nt][0], acc[mt][nt][1]);
                *(float2*)(part + (size_t)(row + 8) * ESZ_ + col) =
                    make_float2(acc[mt][nt][2], acc[mt][nt][3]);
            }
        }
        __syncthreads();
    }
}

// ---------------- K-chunk reduce + bias + L2 normalize; tw0 -> fp16 hi/lo, tw1 -> bf16 ----------------
__global__ __launch_bounds__(128) void reduce_norm_kernel(
    const float* __restrict__ b1, const float* __restrict__ b2)
{
    int row = blockIdx.x;
    int tw  = row >> 11;
    int r   = row & 2047;
    const float* bias = tw ? b2 : b1;
    int t = threadIdx.x;

    float v[4];
    {
        float4 bb = *(const float4*)(bias + t * 4);
        v[0] = bb.x; v[1] = bb.y; v[2] = bb.z; v[3] = bb.w;
    }
    size_t roff = (size_t)r * ESZ_ + t * 4;
    if (tw == 0) {
        float hi[4] = {0, 0, 0, 0}, lo[4] = {0, 0, 0, 0};
        #pragma unroll
        for (int c = 0; c < 2; c++) {
            float4 p = *(const float4*)(g_partk + (size_t)c * B_ * ESZ_ + roff);
            hi[0] += p.x; hi[1] += p.y; hi[2] += p.z; hi[3] += p.w;
        }
        #pragma unroll
        for (int c = 2; c < 4; c++) {
            float4 p = *(const float4*)(g_partk + (size_t)c * B_ * ESZ_ + roff);
            lo[0] += p.x; lo[1] += p.y; lo[2] += p.z; lo[3] += p.w;
        }
        #pragma unroll
        for (int q = 0; q < 4; q++) v[q] += hi[q] + lo[q] * LO_INV;
    } else {
        #pragma unroll
        for (int c = 4; c < 13; c++) {
            float4 p = *(const float4*)(g_partk + (size_t)c * B_ * ESZ_ + roff);
            v[0] += p.x; v[1] += p.y; v[2] += p.z; v[3] += p.w;
        }
    }

    __shared__ float red[128];
    red[t] = v[0] * v[0] + v[1] * v[1] + v[2] * v[2] + v[3] * v[3];
    __syncthreads();
    for (int off = 64; off > 0; off >>= 1) {
        if (t < off) red[t] += red[t + off];
        __syncthreads();
    }
    float inv = 1.0f / (sqrtf(red[0]) + 1e-4f);
    size_t o = (size_t)row * ESZ_ + t * 4;
    if (tw == 0) {
        __half h[4], l[4];
        #pragma unroll
        for (int q = 0; q < 4; q++) {
            float nv = v[q] * inv;
            h[q] = __float2half_rn(nv);
            l[q] = __float2half_rn((nv - __half2float(h[q])) * LO_SCALE);
        }
        *reinterpret_cast<__half2*>(g_eh + o)     = __halves2half2(h[0], h[1]);
        *reinterpret_cast<__half2*>(g_eh + o + 2) = __halves2half2(h[2], h[3]);
        *reinterpret_cast<__half2*>(g_el + o)     = __halves2half2(l[0], l[1]);
        *reinterpret_cast<__half2*>(g_el + o + 2) = __halves2half2(l[2], l[3]);
    } else {
        __nv_bfloat16 h[4], l[4];
        #pragma unroll
        for (int q = 0; q < 4; q++) split_bf16(v[q] * inv, h[q], l[q]);
        *(__nv_bfloat162*)(g_eh + o)     = __nv_bfloat162(h[0], h[1]);
        *(__nv_bfloat162*)(g_eh + o + 2) = __nv_bfloat162(h[2], h[3]);
        *(__nv_bfloat162*)(g_el + o)     = __nv_bfloat162(l[0], l[1]);
        *(__nv_bfloat162*)(g_el + o + 2) = __nv_bfloat162(l[2], l[3]);
    }
}

// ---------------- scores GEMM: bf16 3-term (unchanged numeric path) ----------------
#define OUT_NK 48

__global__ __launch_bounds__(256, 2) void hmma_scores_kernel(
    const __nv_bfloat16* __restrict__ Ah, const __nv_bfloat16* __restrict__ Al,
    const __nv_bfloat16* __restrict__ Bh, const __nv_bfloat16* __restrict__ Bl,
    float* __restrict__ C, int N)
{
    __shared__ __align__(16) __nv_bfloat16 smA[2][128 * APITCH];
    __shared__ __align__(16) __nv_bfloat16 smW[2][128 * APITCH];

    int tid = threadIdx.x;
    int wid = tid >> 5;
    int lid = tid & 31;
    int bn = blockIdx.x * 128;
    int bm = blockIdx.y * 128;

    bool isA = tid < 128;
    int lrow = tid & 127;
    int grow = isA ? (bm + lrow) : (bn + lrow);
    const __nv_bfloat16* srcHi = (isA ? Ah : Bh) + (size_t)grow * ESZ_;
    const __nv_bfloat16* srcLo = (isA ? Al : Bl) + (size_t)grow * ESZ_;
    uint32_t dstBase[2];
    dstBase[0] = smem_u32(isA ? &smA[0][0] : &smW[0][0]) + lrow * (APITCH * 2);
    dstBase[1] = smem_u32(isA ? &smA[1][0] : &smW[1][0]) + lrow * (APITCH * 2);

    auto load_tile = [&](int buf, int kt) {
        int ph = kt >> 4;
        int ko = (kt & 15) * 32;
        const __nv_bfloat16* src =
            (isA ? (ph == 1 ? srcLo : srcHi) : (ph == 2 ? srcLo : srcHi)) + ko;
        uint32_t d = dstBase[buf];
        CP_ASYNC16(d,      src);
        CP_ASYNC16(d + 16, src + 8);
        CP_ASYNC16(d + 32, src + 16);
        CP_ASYNC16(d + 48, src + 24);
        asm volatile("cp.async.commit_group;" ::: "memory");
    };

    int mw = wid & 1, nw = wid >> 1;
    uint32_t aOff[4], bOff[2];
    #pragma unroll
    for (int mt = 0; mt < 4; mt++) {
        int row = mw * 64 + mt * 16 + (lid & 15);
        int k   = (lid >> 4) * 8;
        aOff[mt] = (uint32_t)(row * APITCH + k) * 2;
    }
    #pragma unroll
    for (int p = 0; p < 2; p++) {
        int n = nw * 32 + p * 16 + ((lid >> 4) & 1) * 8 + (lid & 7);
        int k = ((lid >> 3) & 1) * 8;
        bOff[p] = (uint32_t)(n * APITCH + k) * 2;
    }
    uint32_t aBase[2] = { smem_u32(&smA[0][0]), smem_u32(&smA[1][0]) };
    uint32_t bBase[2] = { smem_u32(&smW[0][0]), smem_u32(&smW[1][0]) };

    float acc[4][4][4] = {};

    load_tile(0, 0);
    for (int kt = 0; kt < OUT_NK; kt++) {
        int buf = kt & 1;
        if (kt + 1 < OUT_NK) {
            load_tile(buf ^ 1, kt + 1);
            asm volatile("cp.async.wait_group 1;" ::: "memory");
        } else {
            asm volatile("cp.async.wait_group 0;" ::: "memory");
        }
        __syncthreads();
        do_compute<false>(aBase[buf], bBase[buf], aOff, bOff, acc);
        __syncthreads();
    }

    int g = lid >> 2, tg = lid & 3;
    #pragma unroll
    for (int mt = 0; mt < 4; mt++) {
        int row = bm + mw * 64 + mt * 16 + g;
        #pragma unroll
        for (int nt = 0; nt < 4; nt++) {
            int col = bn + nw * 32 + nt * 8 + tg * 2;
            *(float2*)(C + (size_t)row * N + col) =
                make_float2(acc[mt][nt][0], acc[mt][nt][1]);
            *(float2*)(C + (size_t)(row + 8) * N + col) =
                make_float2(acc[mt][nt][2], acc[mt][nt][3]);
        }
    }
}

// ---------------- final GEMM: fp16 2-term, gathered B rows, exp(scale) ----------------
#define OUTF_NK 32

__global__ __launch_bounds__(256, 2) void hmma_final_f16_kernel(
    const __half* __restrict__ Ah, const __half* __restrict__ Al,
    const __half* __restrict__ Bh, float* __restrict__ C, int N)
{
    __shared__ __align__(16) __nv_bfloat16 smA[2][128 * APITCH];
    __shared__ __align__(16) __nv_bfloat16 smW[2][128 * APITCH];

    int tid = threadIdx.x;
    int wid = tid >> 5;
    int lid = tid & 31;
    int bn = blockIdx.x * 128;
    int bm = blockIdx.y * 128;

    bool isA = tid < 128;
    int lrow = tid & 127;
    int grow = isA ? (bm + lrow) : g_zind[bn + lrow];
    const __half* srcHi = (isA ? Ah : Bh) + (size_t)grow * ESZ_;
    const __half* srcLo = (isA ? Al : Bh) + (size_t)grow * ESZ_;
    uint32_t dstBase[2];
    dstBase[0] = smem_u32(isA ? &smA[0][0] : &smW[0][0]) + lrow * (APITCH * 2);
    dstBase[1] = smem_u32(isA ? &smA[1][0] : &smW[1][0]) + lrow * (APITCH * 2);

    auto load_tile = [&](int buf, int kt) {
        int ph = kt >> 4;                 // 0: A-lo phase, 1: A-hi phase; B always hi
        int ko = (kt & 15) * 32;
        const __half* src = (isA ? (ph == 0 ? srcLo : srcHi) : srcHi) + ko;
        uint32_t d = dstBase[buf];
        CP_ASYNC16(d,      src);
        CP_ASYNC16(d + 16, src + 8);
        CP_ASYNC16(d + 32, src + 16);
        CP_ASYNC16(d + 48, src + 24);
        asm volatile("cp.async.commit_group;" ::: "memory");
    };

    int mw = wid & 1, nw = wid >> 1;
    uint32_t aOff[4], bOff[2];
    #pragma unroll
    for (int mt = 0; mt < 4; mt++) {
        int row = mw * 64 + mt * 16 + (lid & 15);
        int k   = (lid >> 4) * 8;
        aOff[mt] = (uint32_t)(row * APITCH + k) * 2;
    }
    #pragma unroll
    for (int p = 0; p < 2; p++) {
        int n = nw * 32 + p * 16 + ((lid >> 4) & 1) * 8 + (lid & 7);
        int k = ((lid >> 3) & 1) * 8;
        bOff[p] = (uint32_t)(n * APITCH + k) * 2;
    }
    uint32_t aBase[2] = { smem_u32(&smA[0][0]), smem_u32(&smA[1][0]) };
    uint32_t bBase[2] = { smem_u32(&smW[0][0]), smem_u32(&smW[1][0]) };

    float acc[4][4][4] = {};

    load_tile(0, 0);
    for (int kt = 0; kt < OUTF_NK; kt++) {
        int buf = kt & 1;
        if (kt + 1 < OUTF_NK) {
            load_tile(buf ^ 1, kt + 1);
            asm volatile("cp.async.wait_group 1;" ::: "memory");
        } else {
            asm volatile("cp.async.wait_group 0;" ::: "memory");
        }
        __syncthreads();
        do_compute<true>(aBase[buf], bBase[buf], aOff, bOff, acc);
        if (kt == 15) {
            #pragma unroll
            for (int mt = 0; mt < 4; mt++)
                #pragma unroll
                for (int nt = 0; nt < 4; nt++)
                    #pragma unroll
                    for (int q = 0; q < 4; q++)
                        acc[mt][nt][q] *= LO_INV;
        }
        __syncthreads();
    }

    float alpha = g_escale;
    int g = lid >> 2, tg = lid & 3;
    #pragma unroll
    for (int mt = 0; mt < 4; mt++) {
        int row = bm + mw * 64 + mt * 16 + g;
        #pragma unroll
        for (int nt = 0; nt < 4; nt++) {
            int col = bn + nw * 32 + nt * 8 + tg * 2;
            *(float2*)(C + (size_t)row * N + col) =
                make_float2(acc[mt][nt][0] * alpha, acc[mt][nt][1] * alpha);
            *(float2*)(C + (size_t)(row + 8) * N + col) =
                make_float2(acc[mt][nt][2] * alpha, acc[mt][nt][3] * alpha);
        }
    }
}

// ---------------- argmax over scores rows (first-max tie-break) ----------------
__global__ void argmax_kernel()
{
    int r = blockIdx.x, t = threadIdx.x;
    const float* sr = g_scores + (size_t)r * NZ_;
    __shared__ float sv[256];
    __shared__ int   si[256];
    float v0 = sr[t], v1 = sr[t + 256];
    float bv = v0; int bi = t;
    if (v1 > bv) { bv = v1; bi = t + 256; }
    sv[t] = bv; si[t] = bi; __syncthreads();
    for (int off = 128; off > 0; off >>= 1) {
        if (t < off) {
            float ov = sv[t + off]; int oi = si[t + off];
            if (ov > sv[t] || (ov == sv[t] && oi < si[t])) { sv[t] = ov; si[t] = oi; }
        }
        __syncthreads();
    }
    if (t == 0) g_zind[r] = si[0];
}

// ---------------- launch ----------------
extern "C" void kernel_launch(void* const* d_in, const int* in_sizes, int n_in,
                              void* d_out, int out_size)
{
    (void)in_sizes; (void)n_in; (void)out_size;
    const int*   s       = (const int*)d_in[0];
    const int*   sp      = (const int*)d_in[1];
    const float* state_e = (const float*)d_in[2];
    const float* cew     = (const float*)d_in[3];
    const float* ceb     = (const float*)d_in[4];
    const float* p1c1w   = (const float*)d_in[5];
    const float* p1c1b   = (const float*)d_in[6];
    const float* p1c2w   = (const float*)d_in[7];
    const float* p1c2b   = (const float*)d_in[8];
    const float* p1lw    = (const float*)d_in[9];
    const float* p1lb    = (const float*)d_in[10];
    const float* p2c1w   = (const float*)d_in[11];
    const float* p2c1b   = (const float*)d_in[12];
    const float* p2c2w   = (const float*)d_in[13];
    const float* p2c2b   = (const float*)d_in[14];
    const float* p2lw    = (const float*)d_in[15];
    const float* p2lb    = (const float*)d_in[16];
    const float* zv      = (const float*)d_in[17];
    const float* scale   = (const float*)d_in[18];

    void *peh, *pel, *pzh, *pzl, *pzf, *ps, *pp;
    cudaGetSymbolAddress(&peh, g_eh);
    cudaGetSymbolAddress(&pel, g_el);
    cudaGetSymbolAddress(&pzh, g_znh);
    cudaGetSymbolAddress(&pzl, g_znl);
    cudaGetSymbolAddress(&pzf, g_znf);
    cudaGetSymbolAddress(&ps, g_scores);
    cudaGetSymbolAddress(&pp, g_partk);
    __nv_bfloat16* eh  = (__nv_bfloat16*)peh;
    __nv_bfloat16* el  = (__nv_bfloat16*)pel;
    __nv_bfloat16* znh = (__nv_bfloat16*)pzh;
    __nv_bfloat16* znl = (__nv_bfloat16*)pzl;
    __half*        znf = (__half*)pzf;
    float* scores = (float*)ps;
    float* partk  = (float*)pp;

    cudaFuncSetAttribute(tower_kernel,
                         cudaFuncAttributeMaxDynamicSharedMemorySize, TOWER_SMEM_BYTES);

    prep_kernel<<<513, 128>>>(state_e, zv, scale);
    embed_kernel<<<B_, 256>>>(s, sp, cew, ceb);
    wconv_kernel<<<(2 * ESZ_ * 8192 / 4) / 256, 256>>>(p1lw, p2lw);
    tower_kernel<<<dim3(B_, 2), 256, TOWER_SMEM_BYTES>>>(
        p1c1w, p1c1b, p1c2w, p1c2b, p2c1w, p2c1b, p2c2w, p2c2b);

    // zero extra tail slots 10..12 (regions not covered by quarter jobs must read 0)
    cudaMemsetAsync(partk + (size_t)10 * B_ * ESZ_, 0,
                    (size_t)3 * B_ * ESZ_ * sizeof(float));

    // persistent job-queue linear: 592 full jobs (2 exact waves) + 192 quarter tail jobs
    hmma_linear_persist<<<296, 256>>>();

    // K-chunk reduce + bias + normalize -> fp16 (tw0) / bf16 (tw1) hi/lo embeds
    reduce_norm_kernel<<<2 * B_, 128>>>(p1lb, p2lb);

    // scores = embed2 . zn^T (bf16 3-term, numeric path unchanged)
    hmma_scores_kernel<<<dim3(4, 16), 256>>>(
        eh + (size_t)B_ * ESZ_, el + (size_t)B_ * ESZ_, znh, znl, scores, NZ_);

    argmax_kernel<<<B_, 256>>>();

    // out = exp(scale) * embed1 . zn[z_inds]^T (fp16 2-term, gathered B rows)
    hmma_final_f16_kernel<<<dim3(16, 16), 256>>>(
        (const __half*)eh, (const __half*)el, znf, (float*)d_out, B_);
}